// round 12
// baseline (speedup 1.0000x reference)
#include <cuda_runtime.h>
#include <cuda_bf16.h>
#include <math.h>

#define DD 128           // feature dim
#define HH 16            // hidden dim
#define MAXN 131072      // >= N=100000
#define CHUNK 8          // k-columns staged per chunk (32B = 1 sector per row)
#define NCHUNK (DD / CHUNK)
#define NODES_PB 512     // nodes per block (2 per thread)

// Scratch for per-node projections (no cudaMalloc allowed)
__device__ float g_U[(size_t)MAXN * HH];
__device__ float g_V[(size_t)MAXN * HH];

__device__ __forceinline__ unsigned long long fma_f32x2(
    unsigned long long a, unsigned long long b, unsigned long long c)
{
    unsigned long long d;
    asm("fma.rn.f32x2 %0, %1, %2, %3;" : "=l"(d) : "l"(a), "l"(b), "l"(c));
    return d;
}

// ---------------------------------------------------------------------------
// proj: U[n] = z[n] @ W1[0:128] + b1 ; V[n] = z[n] @ W1[128:256]
// 2 nodes per thread (t and t+256) so each weight-row LDS feeds 2x FMA2.
// z staged through smem in sector-efficient CHUNK=8 slices, pad-9 rows
// (stride 9 floats between lanes -> gcd(9,32)=1 -> conflict-free readback).
// ---------------------------------------------------------------------------
__global__ __launch_bounds__(256) void proj_kernel(
    const float* __restrict__ z, const float* __restrict__ W1,
    const float* __restrict__ b1, int N)
{
    __shared__ float sWf[2 * DD * HH];            // 16 KB weights
    __shared__ float sb[HH];
    __shared__ float sZ[NODES_PB * (CHUNK + 1)];  // 18.4 KB staged z

    const int tid = threadIdx.x;
    {
        const float4* src = reinterpret_cast<const float4*>(W1);
        float4* dst = reinterpret_cast<float4*>(sWf);
        for (int i = tid; i < (2 * DD * HH) / 4; i += blockDim.x) dst[i] = src[i];
        if (tid < HH) sb[tid] = b1[tid];
    }
    __syncthreads();

    const int n_base = blockIdx.x * NODES_PB;
    const int nA = n_base + tid;
    const int nB = n_base + 256 + tid;

    // packed f32x2 accumulators for both nodes
    unsigned long long uA[HH / 2], vA[HH / 2], uB[HH / 2], vB[HH / 2];
#pragma unroll
    for (int j = 0; j < HH / 2; j++) {
        unsigned long long bb;
        asm("mov.b64 %0, {%1, %2};" : "=l"(bb) : "f"(sb[2 * j]), "f"(sb[2 * j + 1]));
        uA[j] = bb; uB[j] = bb;
        asm("mov.b64 %0, {%1, %2};" : "=l"(vA[j]) : "f"(0.0f), "f"(0.0f));
        vB[j] = vA[j];
    }

    const ulonglong2* sW2 = reinterpret_cast<const ulonglong2*>(sWf);
    const bool full_tile = (n_base + NODES_PB <= N);

#pragma unroll 1
    for (int kc = 0; kc < NCHUNK; kc++) {
        if (kc) __syncthreads();
        // Stage NODES_PB x CHUNK floats; each 8-lane group reads one 32B sector.
        if (full_tile) {
#pragma unroll
            for (int i = 0; i < (NODES_PB * CHUNK) / 256; i++) {
                int idx = tid + i * 256;
                int r = idx >> 3, c = idx & (CHUNK - 1);
                sZ[r * (CHUNK + 1) + c] = z[(size_t)(n_base + r) * DD + kc * CHUNK + c];
            }
        } else {
#pragma unroll
            for (int i = 0; i < (NODES_PB * CHUNK) / 256; i++) {
                int idx = tid + i * 256;
                int r = idx >> 3, c = idx & (CHUNK - 1);
                int nn = n_base + r;
                sZ[r * (CHUNK + 1) + c] =
                    (nn < N) ? z[(size_t)nn * DD + kc * CHUNK + c] : 0.0f;
            }
        }
        __syncthreads();

        const float* zrA = &sZ[tid * (CHUNK + 1)];
        const float* zrB = &sZ[(256 + tid) * (CHUNK + 1)];
#pragma unroll
        for (int kk = 0; kk < CHUNK; kk++) {
            const int k = kc * CHUNK + kk;
            unsigned long long zA2, zB2;
            asm("mov.b64 %0, {%1, %1};" : "=l"(zA2) : "f"(zrA[kk]));
            asm("mov.b64 %0, {%1, %1};" : "=l"(zB2) : "f"(zrB[kk]));
            const ulonglong2* wu = sW2 + (size_t)k * (HH / 4);
            const ulonglong2* wv = sW2 + (size_t)(DD + k) * (HH / 4);
#pragma unroll
            for (int j = 0; j < HH / 4; j++) {
                ulonglong2 a = wu[j];
                uA[2 * j]     = fma_f32x2(zA2, a.x, uA[2 * j]);
                uA[2 * j + 1] = fma_f32x2(zA2, a.y, uA[2 * j + 1]);
                uB[2 * j]     = fma_f32x2(zB2, a.x, uB[2 * j]);
                uB[2 * j + 1] = fma_f32x2(zB2, a.y, uB[2 * j + 1]);
                ulonglong2 b = wv[j];
                vA[2 * j]     = fma_f32x2(zA2, b.x, vA[2 * j]);
                vA[2 * j + 1] = fma_f32x2(zA2, b.y, vA[2 * j + 1]);
                vB[2 * j]     = fma_f32x2(zB2, b.x, vB[2 * j]);
                vB[2 * j + 1] = fma_f32x2(zB2, b.y, vB[2 * j + 1]);
            }
        }
    }

    if (nA < N) {
        ulonglong2* Up = reinterpret_cast<ulonglong2*>(&g_U[(size_t)nA * HH]);
        ulonglong2* Vp = reinterpret_cast<ulonglong2*>(&g_V[(size_t)nA * HH]);
#pragma unroll
        for (int j = 0; j < HH / 4; j++) {
            Up[j] = make_ulonglong2(uA[2 * j], uA[2 * j + 1]);
            Vp[j] = make_ulonglong2(vA[2 * j], vA[2 * j + 1]);
        }
    }
    if (nB < N) {
        ulonglong2* Up = reinterpret_cast<ulonglong2*>(&g_U[(size_t)nB * HH]);
        ulonglong2* Vp = reinterpret_cast<ulonglong2*>(&g_V[(size_t)nB * HH]);
#pragma unroll
        for (int j = 0; j < HH / 4; j++) {
            Up[j] = make_ulonglong2(uB[2 * j], uB[2 * j + 1]);
            Vp[j] = make_ulonglong2(vB[2 * j], vB[2 * j + 1]);
        }
    }
}

// ---------------------------------------------------------------------------
// edge: 4 edges per warp, 8 lanes per edge (R8 version — 44.2us proven;
// the MLP head hides entirely under the adj gather latency).
// ---------------------------------------------------------------------------
__global__ __launch_bounds__(256) void edge_kernel(
    const float* __restrict__ z, const int* __restrict__ ei,
    const float* __restrict__ W2, const float* __restrict__ b2,
    float* __restrict__ out, int E)
{
    int tid  = blockIdx.x * blockDim.x + threadIdx.x;
    int warp = tid >> 5;
    int lane = threadIdx.x & 31;
    int sub  = lane >> 3;       // which of 4 edges this lane serves
    int sl   = lane & 7;        // lane within the 8-lane group

    int e = warp * 4 + sub;
    if (e >= E) return;

    int r = __ldg(&ei[e]);
    int c = __ldg(&ei[(size_t)E + e]);

    const float4* zr4 = reinterpret_cast<const float4*>(z) + (size_t)r * (DD / 4);
    const float4* zc4 = reinterpret_cast<const float4*>(z) + (size_t)c * (DD / 4);
    float4 a0 = __ldg(&zr4[sl]);
    float4 a1 = __ldg(&zr4[sl + 8]);
    float4 a2 = __ldg(&zr4[sl + 16]);
    float4 a3 = __ldg(&zr4[sl + 24]);
    float4 b0 = __ldg(&zc4[sl]);
    float4 b1v = __ldg(&zc4[sl + 8]);
    float4 b2v = __ldg(&zc4[sl + 16]);
    float4 b3 = __ldg(&zc4[sl + 24]);

    float p = a0.x * b0.x;
    p = fmaf(a0.y, b0.y, p);  p = fmaf(a0.z, b0.z, p);  p = fmaf(a0.w, b0.w, p);
    p = fmaf(a1.x, b1v.x, p); p = fmaf(a1.y, b1v.y, p);
    p = fmaf(a1.z, b1v.z, p); p = fmaf(a1.w, b1v.w, p);
    p = fmaf(a2.x, b2v.x, p); p = fmaf(a2.y, b2v.y, p);
    p = fmaf(a2.z, b2v.z, p); p = fmaf(a2.w, b2v.w, p);
    p = fmaf(a3.x, b3.x, p);  p = fmaf(a3.y, b3.y, p);
    p = fmaf(a3.z, b3.z, p);  p = fmaf(a3.w, b3.w, p);

    // --- MLP head: each lane owns 2 of the 16 hidden units ---
    const float2 uu = *reinterpret_cast<const float2*>(&g_U[(size_t)r * HH + 2 * sl]);
    const float2 vv = *reinterpret_cast<const float2*>(&g_V[(size_t)c * HH + 2 * sl]);
    const float2 w2 = __ldg(reinterpret_cast<const float2*>(&W2[2 * sl]));
    float h0 = fmaxf(uu.x + vv.x, 0.0f);
    float h1 = fmaxf(uu.y + vv.y, 0.0f);
    float q = fmaf(h1, w2.y, h0 * w2.x);

#pragma unroll
    for (int off = 4; off > 0; off >>= 1) {
        p += __shfl_xor_sync(0xffffffffu, p, off);
        q += __shfl_xor_sync(0xffffffffu, q, off);
    }

    if (sl == 0) {
        out[e] = p;
        float x = q + __ldg(&b2[0]);
        // stable softplus: max(x,0) + log1p(exp(-|x|))
        out[(size_t)E + e] = fmaxf(x, 0.0f) + log1pf(expf(-fabsf(x)));
    }
}

extern "C" void kernel_launch(void* const* d_in, const int* in_sizes, int n_in,
                              void* d_out, int out_size)
{
    const float* z  = (const float*)d_in[0];
    const int*   ei = (const int*)d_in[1];
    const float* W1 = (const float*)d_in[2];
    const float* b1 = (const float*)d_in[3];
    const float* W2 = (const float*)d_in[4];
    const float* b2 = (const float*)d_in[5];
    float*       out = (float*)d_out;

    int N = in_sizes[0] / DD;       // 100000
    int E = in_sizes[1] / 2;        // 600000

    // Kernel 1: per-node projections (2 nodes/thread)
    {
        int blocks = (N + NODES_PB - 1) / NODES_PB;   // 196
        proj_kernel<<<blocks, 256>>>(z, W1, b1, N);
    }
    // Kernel 2: per-edge outputs (4 edges/warp, MLP head fused)
    {
        int blocks = (E + 31) / 32;                   // 18750
        edge_kernel<<<blocks, 256>>>(z, ei, W2, b2, out, E);
    }
}

// round 13
// speedup vs baseline: 1.7920x; 1.7920x over previous
#include <cuda_runtime.h>
#include <cuda_bf16.h>
#include <math.h>

#define DD 128           // feature dim
#define HH 16            // hidden dim
#define MAXN 131072      // >= N=100000
#define CHUNK 16         // k-columns staged per chunk
#define NCHUNK (DD / CHUNK)
#define NODES_PB 512     // nodes per block (2 per thread)

// Scratch for per-node projections (no cudaMalloc allowed)
__device__ float g_U[(size_t)MAXN * HH];
__device__ float g_V[(size_t)MAXN * HH];

__device__ __forceinline__ unsigned long long fma_f32x2(
    unsigned long long a, unsigned long long b, unsigned long long c)
{
    unsigned long long d;
    asm("fma.rn.f32x2 %0, %1, %2, %3;" : "=l"(d) : "l"(a), "l"(b), "l"(c));
    return d;
}

// ---------------------------------------------------------------------------
// proj: U[n] = z[n] @ W1[0:128] + b1 ; V[n] = z[n] @ W1[128:256]
// 2 nodes per thread (tid and tid+256): each warp-uniform weight LDS.128
// feeds 4 FMA2 instead of 2. z staged in coalesced CHUNK=16 slices
// (16 lanes cover 64B of one row -> 2 lines per warp staging instr),
// pad-17 rows: gcd(17,32)=1 -> conflict-free scalar readback; the +256-row
// offset is 256*17 = 4352 = 0 mod 32 -> also conflict-free.
// ---------------------------------------------------------------------------
__global__ __launch_bounds__(256) void proj_kernel(
    const float* __restrict__ z, const float* __restrict__ W1,
    const float* __restrict__ b1, int N)
{
    __shared__ float sWf[2 * DD * HH];              // 16 KB weights
    __shared__ float sb[HH];
    __shared__ float sZ[NODES_PB * (CHUNK + 1)];    // 34.8 KB staged z

    const int tid = threadIdx.x;
    {
        const float4* src = reinterpret_cast<const float4*>(W1);
        float4* dst = reinterpret_cast<float4*>(sWf);
        for (int i = tid; i < (2 * DD * HH) / 4; i += blockDim.x) dst[i] = src[i];
        if (tid < HH) sb[tid] = b1[tid];
    }
    __syncthreads();

    const int n_base = blockIdx.x * NODES_PB;
    const int nA = n_base + tid;
    const int nB = n_base + 256 + tid;

    // packed f32x2 accumulators for both nodes
    unsigned long long uA[HH / 2], vA[HH / 2], uB[HH / 2], vB[HH / 2];
#pragma unroll
    for (int j = 0; j < HH / 2; j++) {
        unsigned long long bb;
        asm("mov.b64 %0, {%1, %2};" : "=l"(bb) : "f"(sb[2 * j]), "f"(sb[2 * j + 1]));
        uA[j] = bb; uB[j] = bb;
        asm("mov.b64 %0, {%1, %2};" : "=l"(vA[j]) : "f"(0.0f), "f"(0.0f));
        vB[j] = vA[j];
    }

    const ulonglong2* sW2 = reinterpret_cast<const ulonglong2*>(sWf);
    const bool full_tile = (n_base + NODES_PB <= N);

#pragma unroll 1
    for (int kc = 0; kc < NCHUNK; kc++) {
        if (kc) __syncthreads();
        // Stage NODES_PB x CHUNK floats; 16 lanes read 64B of one row.
        if (full_tile) {
#pragma unroll
            for (int i = 0; i < (NODES_PB * CHUNK) / 256; i++) {
                int idx = tid + i * 256;
                int r = idx >> 4, c = idx & (CHUNK - 1);
                sZ[r * (CHUNK + 1) + c] = z[(size_t)(n_base + r) * DD + kc * CHUNK + c];
            }
        } else {
#pragma unroll
            for (int i = 0; i < (NODES_PB * CHUNK) / 256; i++) {
                int idx = tid + i * 256;
                int r = idx >> 4, c = idx & (CHUNK - 1);
                int nn = n_base + r;
                sZ[r * (CHUNK + 1) + c] =
                    (nn < N) ? z[(size_t)nn * DD + kc * CHUNK + c] : 0.0f;
            }
        }
        __syncthreads();

        const float* zrA = &sZ[tid * (CHUNK + 1)];
        const float* zrB = &sZ[(256 + tid) * (CHUNK + 1)];
#pragma unroll
        for (int kk = 0; kk < CHUNK; kk++) {
            const int k = kc * CHUNK + kk;
            unsigned long long zA2, zB2;
            asm("mov.b64 %0, {%1, %1};" : "=l"(zA2) : "f"(zrA[kk]));
            asm("mov.b64 %0, {%1, %1};" : "=l"(zB2) : "f"(zrB[kk]));
            const ulonglong2* wu = sW2 + (size_t)k * (HH / 4);
            const ulonglong2* wv = sW2 + (size_t)(DD + k) * (HH / 4);
#pragma unroll
            for (int j = 0; j < HH / 4; j++) {
                ulonglong2 a = wu[j];
                uA[2 * j]     = fma_f32x2(zA2, a.x, uA[2 * j]);
                uA[2 * j + 1] = fma_f32x2(zA2, a.y, uA[2 * j + 1]);
                uB[2 * j]     = fma_f32x2(zB2, a.x, uB[2 * j]);
                uB[2 * j + 1] = fma_f32x2(zB2, a.y, uB[2 * j + 1]);
                ulonglong2 b = wv[j];
                vA[2 * j]     = fma_f32x2(zA2, b.x, vA[2 * j]);
                vA[2 * j + 1] = fma_f32x2(zA2, b.y, vA[2 * j + 1]);
                vB[2 * j]     = fma_f32x2(zB2, b.x, vB[2 * j]);
                vB[2 * j + 1] = fma_f32x2(zB2, b.y, vB[2 * j + 1]);
            }
        }
    }

    if (nA < N) {
        ulonglong2* Up = reinterpret_cast<ulonglong2*>(&g_U[(size_t)nA * HH]);
        ulonglong2* Vp = reinterpret_cast<ulonglong2*>(&g_V[(size_t)nA * HH]);
#pragma unroll
        for (int j = 0; j < HH / 4; j++) {
            Up[j] = make_ulonglong2(uA[2 * j], uA[2 * j + 1]);
            Vp[j] = make_ulonglong2(vA[2 * j], vA[2 * j + 1]);
        }
    }
    if (nB < N) {
        ulonglong2* Up = reinterpret_cast<ulonglong2*>(&g_U[(size_t)nB * HH]);
        ulonglong2* Vp = reinterpret_cast<ulonglong2*>(&g_V[(size_t)nB * HH]);
#pragma unroll
        for (int j = 0; j < HH / 4; j++) {
            Up[j] = make_ulonglong2(uB[2 * j], uB[2 * j + 1]);
            Vp[j] = make_ulonglong2(vB[2 * j], vB[2 * j + 1]);
        }
    }
}

// ---------------------------------------------------------------------------
// edge: 4 edges per warp, 8 lanes per edge (EXACT R8 version, 44.2us proven;
// the MLP head hides entirely under the adj gather latency).
// ---------------------------------------------------------------------------
__global__ __launch_bounds__(256) void edge_kernel(
    const float* __restrict__ z, const int* __restrict__ ei,
    const float* __restrict__ W2, const float* __restrict__ b2,
    float* __restrict__ out, int E)
{
    int tid  = blockIdx.x * blockDim.x + threadIdx.x;
    int warp = tid >> 5;
    int lane = threadIdx.x & 31;
    int sub  = lane >> 3;       // which of 4 edges this lane serves
    int sl   = lane & 7;        // lane within the 8-lane group

    int e = warp * 4 + sub;
    if (e >= E) return;

    int r = __ldg(&ei[e]);
    int c = __ldg(&ei[(size_t)E + e]);

    const float4* zr4 = reinterpret_cast<const float4*>(z) + (size_t)r * (DD / 4);
    const float4* zc4 = reinterpret_cast<const float4*>(z) + (size_t)c * (DD / 4);
    float4 a0 = __ldg(&zr4[sl]);
    float4 a1 = __ldg(&zr4[sl + 8]);
    float4 a2 = __ldg(&zr4[sl + 16]);
    float4 a3 = __ldg(&zr4[sl + 24]);
    float4 b0 = __ldg(&zc4[sl]);
    float4 b1v = __ldg(&zc4[sl + 8]);
    float4 b2v = __ldg(&zc4[sl + 16]);
    float4 b3 = __ldg(&zc4[sl + 24]);

    float p = a0.x * b0.x;
    p = fmaf(a0.y, b0.y, p);  p = fmaf(a0.z, b0.z, p);  p = fmaf(a0.w, b0.w, p);
    p = fmaf(a1.x, b1v.x, p); p = fmaf(a1.y, b1v.y, p);
    p = fmaf(a1.z, b1v.z, p); p = fmaf(a1.w, b1v.w, p);
    p = fmaf(a2.x, b2v.x, p); p = fmaf(a2.y, b2v.y, p);
    p = fmaf(a2.z, b2v.z, p); p = fmaf(a2.w, b2v.w, p);
    p = fmaf(a3.x, b3.x, p);  p = fmaf(a3.y, b3.y, p);
    p = fmaf(a3.z, b3.z, p);  p = fmaf(a3.w, b3.w, p);

    // --- MLP head: each lane owns 2 of the 16 hidden units ---
    const float2 uu = *reinterpret_cast<const float2*>(&g_U[(size_t)r * HH + 2 * sl]);
    const float2 vv = *reinterpret_cast<const float2*>(&g_V[(size_t)c * HH + 2 * sl]);
    const float2 w2 = __ldg(reinterpret_cast<const float2*>(&W2[2 * sl]));
    float h0 = fmaxf(uu.x + vv.x, 0.0f);
    float h1 = fmaxf(uu.y + vv.y, 0.0f);
    float q = fmaf(h1, w2.y, h0 * w2.x);

#pragma unroll
    for (int off = 4; off > 0; off >>= 1) {
        p += __shfl_xor_sync(0xffffffffu, p, off);
        q += __shfl_xor_sync(0xffffffffu, q, off);
    }

    if (sl == 0) {
        out[e] = p;
        float x = q + __ldg(&b2[0]);
        // stable softplus: max(x,0) + log1p(exp(-|x|))
        out[(size_t)E + e] = fmaxf(x, 0.0f) + log1pf(expf(-fabsf(x)));
    }
}

extern "C" void kernel_launch(void* const* d_in, const int* in_sizes, int n_in,
                              void* d_out, int out_size)
{
    const float* z  = (const float*)d_in[0];
    const int*   ei = (const int*)d_in[1];
    const float* W1 = (const float*)d_in[2];
    const float* b1 = (const float*)d_in[3];
    const float* W2 = (const float*)d_in[4];
    const float* b2 = (const float*)d_in[5];
    float*       out = (float*)d_out;

    int N = in_sizes[0] / DD;       // 100000
    int E = in_sizes[1] / 2;        // 600000

    // Kernel 1: per-node projections (2 nodes/thread, staged z)
    {
        int blocks = (N + NODES_PB - 1) / NODES_PB;   // 196
        proj_kernel<<<blocks, 256>>>(z, W1, b1, N);
    }
    // Kernel 2: per-edge outputs (4 edges/warp, MLP head fused)
    {
        int blocks = (E + 31) / 32;                   // 18750
        edge_kernel<<<blocks, 256>>>(z, ei, W2, b2, out, E);
    }
}

// round 14
// speedup vs baseline: 2.1103x; 1.1776x over previous
#include <cuda_runtime.h>
#include <cuda_bf16.h>
#include <math.h>

#define DD 128           // feature dim
#define HH 16            // hidden dim
#define MAXN 131072      // >= N=100000
#define CHUNK 32         // k-columns staged per chunk (R10 proven)

// Scratch for per-node projections (no cudaMalloc allowed)
__device__ float g_U[(size_t)MAXN * HH];
__device__ float g_V[(size_t)MAXN * HH];

__device__ __forceinline__ unsigned long long fma_f32x2(
    unsigned long long a, unsigned long long b, unsigned long long c)
{
    unsigned long long d;
    asm("fma.rn.f32x2 %0, %1, %2, %3;" : "=l"(d) : "l"(a), "l"(b), "l"(c));
    return d;
}

// ---------------------------------------------------------------------------
// proj (R10 exact, ~28us proven): U[n] = z[n]@W1_top + b1 ; V[n] = z[n]@W1_bot
// z staged through smem in coalesced 256x32 chunks (1 line per warp-instr),
// read back conflict-free (pad-33). Packed f32x2 FMA (2 MACs/instr).
// ---------------------------------------------------------------------------
__global__ __launch_bounds__(256) void proj_kernel(
    const float* __restrict__ z, const float* __restrict__ W1,
    const float* __restrict__ b1, int N)
{
    __shared__ float sWf[2 * DD * HH];       // 16 KB weights
    __shared__ float sb[HH];
    __shared__ float sZ[256 * 33];           // 33 KB z chunk (pad 33)

    {
        const float4* src = reinterpret_cast<const float4*>(W1);
        float4* dst = reinterpret_cast<float4*>(sWf);
        for (int i = threadIdx.x; i < (2 * DD * HH) / 4; i += blockDim.x) dst[i] = src[i];
        if (threadIdx.x < HH) sb[threadIdx.x] = b1[threadIdx.x];
    }
    __syncthreads();

    const int tid = threadIdx.x;
    const int n_base = blockIdx.x * 256;
    const int n = n_base + tid;

    // accumulators as packed f32x2 (8 pairs each for u and v)
    unsigned long long u2[HH / 2], v2[HH / 2];
#pragma unroll
    for (int j = 0; j < HH / 2; j++) {
        asm("mov.b64 %0, {%1, %2};" : "=l"(u2[j]) : "f"(sb[2 * j]), "f"(sb[2 * j + 1]));
        asm("mov.b64 %0, {%1, %2};" : "=l"(v2[j]) : "f"(0.0f), "f"(0.0f));
    }

    const ulonglong2* sW2 = reinterpret_cast<const ulonglong2*>(sWf);
    const bool full_tile = (n_base + 256 <= N);

#pragma unroll 1
    for (int kc = 0; kc < DD / CHUNK; kc++) {
        if (kc) __syncthreads();   // previous chunk's readers done
        // Stage 256 nodes x 32 k-values; each warp-iteration reads ONE 128B line.
        if (full_tile) {
#pragma unroll
            for (int i = 0; i < CHUNK; i++) {
                int idx = tid + i * 256;            // 0..8191
                int r = idx >> 5, c = idx & 31;
                sZ[r * 33 + c] = z[(size_t)(n_base + r) * DD + kc * CHUNK + c];
            }
        } else {
#pragma unroll
            for (int i = 0; i < CHUNK; i++) {
                int idx = tid + i * 256;
                int r = idx >> 5, c = idx & 31;
                int nn = n_base + r;
                sZ[r * 33 + c] = (nn < N) ? z[(size_t)nn * DD + kc * CHUNK + c] : 0.0f;
            }
        }
        __syncthreads();

        const float* myz = &sZ[tid * 33];
#pragma unroll
        for (int kk = 0; kk < CHUNK; kk++) {
            int k = kc * CHUNK + kk;
            float zk = myz[kk];
            unsigned long long zk2;
            asm("mov.b64 %0, {%1, %1};" : "=l"(zk2) : "f"(zk));
            const ulonglong2* wu = sW2 + (size_t)k * (HH / 4);
            const ulonglong2* wv = sW2 + (size_t)(DD + k) * (HH / 4);
#pragma unroll
            for (int j = 0; j < HH / 4; j++) {
                ulonglong2 a = wu[j];
                u2[2 * j]     = fma_f32x2(zk2, a.x, u2[2 * j]);
                u2[2 * j + 1] = fma_f32x2(zk2, a.y, u2[2 * j + 1]);
                ulonglong2 b = wv[j];
                v2[2 * j]     = fma_f32x2(zk2, b.x, v2[2 * j]);
                v2[2 * j + 1] = fma_f32x2(zk2, b.y, v2[2 * j + 1]);
            }
        }
    }

    if (n < N) {
        ulonglong2* Up = reinterpret_cast<ulonglong2*>(&g_U[(size_t)n * HH]);
        ulonglong2* Vp = reinterpret_cast<ulonglong2*>(&g_V[(size_t)n * HH]);
#pragma unroll
        for (int j = 0; j < HH / 4; j++) {
            Up[j] = make_ulonglong2(u2[2 * j], u2[2 * j + 1]);
            Vp[j] = make_ulonglong2(v2[2 * j], v2[2 * j + 1]);
        }
    }
}

// ---------------------------------------------------------------------------
// edge (R8 exact, 43-44us proven): 4 edges per warp, 8 lanes per edge.
//   adj[e]    = dot(z[row], z[col])
//   weight[e] = softplus(relu(U[row]+V[col]) @ W2 + b2)   (hides under gather)
// ---------------------------------------------------------------------------
__global__ __launch_bounds__(256) void edge_kernel(
    const float* __restrict__ z, const int* __restrict__ ei,
    const float* __restrict__ W2, const float* __restrict__ b2,
    float* __restrict__ out, int E)
{
    int tid  = blockIdx.x * blockDim.x + threadIdx.x;
    int warp = tid >> 5;
    int lane = threadIdx.x & 31;
    int sub  = lane >> 3;       // which of 4 edges this lane serves
    int sl   = lane & 7;        // lane within the 8-lane group

    int e = warp * 4 + sub;
    if (e >= E) return;

    int r = __ldg(&ei[e]);
    int c = __ldg(&ei[(size_t)E + e]);

    const float4* zr4 = reinterpret_cast<const float4*>(z) + (size_t)r * (DD / 4);
    const float4* zc4 = reinterpret_cast<const float4*>(z) + (size_t)c * (DD / 4);
    float4 a0 = __ldg(&zr4[sl]);
    float4 a1 = __ldg(&zr4[sl + 8]);
    float4 a2 = __ldg(&zr4[sl + 16]);
    float4 a3 = __ldg(&zr4[sl + 24]);
    float4 b0 = __ldg(&zc4[sl]);
    float4 b1v = __ldg(&zc4[sl + 8]);
    float4 b2v = __ldg(&zc4[sl + 16]);
    float4 b3 = __ldg(&zc4[sl + 24]);

    float p = a0.x * b0.x;
    p = fmaf(a0.y, b0.y, p);  p = fmaf(a0.z, b0.z, p);  p = fmaf(a0.w, b0.w, p);
    p = fmaf(a1.x, b1v.x, p); p = fmaf(a1.y, b1v.y, p);
    p = fmaf(a1.z, b1v.z, p); p = fmaf(a1.w, b1v.w, p);
    p = fmaf(a2.x, b2v.x, p); p = fmaf(a2.y, b2v.y, p);
    p = fmaf(a2.z, b2v.z, p); p = fmaf(a2.w, b2v.w, p);
    p = fmaf(a3.x, b3.x, p);  p = fmaf(a3.y, b3.y, p);
    p = fmaf(a3.z, b3.z, p);  p = fmaf(a3.w, b3.w, p);

    // --- MLP head: each lane owns 2 of the 16 hidden units ---
    const float2 uu = *reinterpret_cast<const float2*>(&g_U[(size_t)r * HH + 2 * sl]);
    const float2 vv = *reinterpret_cast<const float2*>(&g_V[(size_t)c * HH + 2 * sl]);
    const float2 w2 = __ldg(reinterpret_cast<const float2*>(&W2[2 * sl]));
    float h0 = fmaxf(uu.x + vv.x, 0.0f);
    float h1 = fmaxf(uu.y + vv.y, 0.0f);
    float q = fmaf(h1, w2.y, h0 * w2.x);

#pragma unroll
    for (int off = 4; off > 0; off >>= 1) {
        p += __shfl_xor_sync(0xffffffffu, p, off);
        q += __shfl_xor_sync(0xffffffffu, q, off);
    }

    if (sl == 0) {
        out[e] = p;
        float x = q + __ldg(&b2[0]);
        // stable softplus: max(x,0) + log1p(exp(-|x|))
        out[(size_t)E + e] = fmaxf(x, 0.0f) + log1pf(expf(-fabsf(x)));
    }
}

extern "C" void kernel_launch(void* const* d_in, const int* in_sizes, int n_in,
                              void* d_out, int out_size)
{
    const float* z  = (const float*)d_in[0];
    const int*   ei = (const int*)d_in[1];
    const float* W1 = (const float*)d_in[2];
    const float* b1 = (const float*)d_in[3];
    const float* W2 = (const float*)d_in[4];
    const float* b2 = (const float*)d_in[5];
    float*       out = (float*)d_out;

    int N = in_sizes[0] / DD;       // 100000
    int E = in_sizes[1] / 2;        // 600000

    // Kernel 1: per-node projections (R10 staged version)
    {
        int blocks = (N + 255) / 256;   // 391
        proj_kernel<<<blocks, 256>>>(z, W1, b1, N);
    }
    // Kernel 2: per-edge outputs (4 edges/warp, MLP head fused)
    {
        int blocks = (E + 31) / 32;     // 18750
        edge_kernel<<<blocks, 256>>>(z, ei, W2, b2, out, E);
    }
}